// round 1
// baseline (speedup 1.0000x reference)
#include <cuda_runtime.h>
#include <math_constants.h>

#define NN 50000
#define EE 1600000
#define DD 128
#define NEG_SLOPE 0.01f

// Scratch (no allocation allowed -> __device__ globals)
__device__ float g_h_cur[NN * DD];   // normalized features, gather source
__device__ float g_h_acc[NN * DD];   // weighted-sum accumulator
__device__ float g_ebuf[EE];         // per-edge leakyrelu score
__device__ float g_ssrc[NN];
__device__ float g_sdst[NN];
__device__ float g_m[NN];            // segment max
__device__ float g_ssum[NN];         // segment sum of exp

__device__ __forceinline__ float atomicMaxF(float* addr, float value) {
    // Monotonic bit-trick: int-max for non-negative, uint-min for negative.
    if (value >= 0.f)
        return __int_as_float(atomicMax((int*)addr, __float_as_int(value)));
    else
        return __uint_as_float(atomicMin((unsigned int*)addr, __float_as_uint(value)));
}

// K1: one warp per node. Normalize previous layer output (or copy input),
// compute s_src/s_dst dots against this layer's attention weights,
// reset m/ssum and zero the accumulator row.
__global__ void k_prep(const float* __restrict__ h_ext, int use_acc,
                       const float* __restrict__ w_row, int n) {
    int gid  = blockIdx.x * blockDim.x + threadIdx.x;
    int node = gid >> 5;
    int lane = threadIdx.x & 31;
    if (node >= n) return;

    float inv = 1.f;
    const float4* src4;
    if (use_acc) {
        float s = g_ssum[node];
        inv  = (s != 0.f) ? 1.f / s : 0.f;
        src4 = (const float4*)g_h_acc;
    } else {
        src4 = (const float4*)h_ext;
    }
    float4 v = src4[node * 32 + lane];
    v.x *= inv; v.y *= inv; v.z *= inv; v.w *= inv;

    ((float4*)g_h_cur)[node * 32 + lane] = v;
    ((float4*)g_h_acc)[node * 32 + lane] = make_float4(0.f, 0.f, 0.f, 0.f);

    float4 ws = ((const float4*)w_row)[lane];        // w_src chunk
    float4 wd = ((const float4*)w_row)[32 + lane];   // w_dst chunk
    float ds = v.x * ws.x + v.y * ws.y + v.z * ws.z + v.w * ws.w;
    float dd = v.x * wd.x + v.y * wd.y + v.z * wd.z + v.w * wd.w;
    #pragma unroll
    for (int o = 16; o; o >>= 1) {
        ds += __shfl_xor_sync(0xffffffffu, ds, o);
        dd += __shfl_xor_sync(0xffffffffu, dd, o);
    }
    if (lane == 0) {
        g_ssrc[node] = ds;
        g_sdst[node] = dd;
        g_m[node]    = -CUDART_INF_F;
        g_ssum[node] = 0.f;
    }
}

// K2: one thread per edge. Scalar score + segment max.
__global__ void k_edge_max(const int* __restrict__ src, const int* __restrict__ dst, int e) {
    int i = blockIdx.x * blockDim.x + threadIdx.x;
    if (i >= e) return;
    int si = src[i], di = dst[i];
    float a  = g_ssrc[si] + g_sdst[di];
    float ev = (a > 0.f) ? a : NEG_SLOPE * a;
    g_ebuf[i] = ev;
    atomicMaxF(&g_m[di], ev);
}

// K3: one warp per edge. exp + segment-sum (lane 0), then vectorized
// weighted feature aggregation with red.global.add.v4.f32.
__global__ void k_edge_agg(const int* __restrict__ src, const int* __restrict__ dst, int e) {
    int gw   = (blockIdx.x * blockDim.x + threadIdx.x) >> 5;
    int lane = threadIdx.x & 31;
    if (gw >= e) return;
    int s = src[gw];
    int d = dst[gw];
    float ex = 0.f;
    if (lane == 0) {
        ex = __expf(g_ebuf[gw] - g_m[d]);
        atomicAdd(&g_ssum[d], ex);
    }
    ex = __shfl_sync(0xffffffffu, ex, 0);

    float4 v = ((const float4*)g_h_cur)[s * 32 + lane];
    float rx = v.x * ex, ry = v.y * ex, rz = v.z * ex, rw = v.w * ex;
    float* p = &g_h_acc[d * DD + lane * 4];
    asm volatile("red.global.add.v4.f32 [%0], {%1,%2,%3,%4};"
                 :: "l"(p), "f"(rx), "f"(ry), "f"(rz), "f"(rw)
                 : "memory");
}

// K5: final normalization into d_out.
__global__ void k_final(float* __restrict__ out, int n) {
    int gid = blockIdx.x * blockDim.x + threadIdx.x;  // over n*32 float4s
    if (gid >= n * 32) return;
    int node = gid >> 5;
    float s   = g_ssum[node];
    float inv = (s != 0.f) ? 1.f / s : 0.f;
    float4 v = ((const float4*)g_h_acc)[gid];
    v.x *= inv; v.y *= inv; v.z *= inv; v.w *= inv;
    ((float4*)out)[gid] = v;
}

extern "C" void kernel_launch(void* const* d_in, const int* in_sizes, int n_in,
                              void* d_out, int out_size) {
    const float* h   = (const float*)d_in[0];
    const int*   src = (const int*)d_in[1];
    const int*   dst = (const int*)d_in[2];
    const float* att = (const float*)d_in[3];
    int n = in_sizes[0] / DD;
    int e = in_sizes[1];

    int prep_blocks = (n * 32 + 255) / 256;
    int edge_blocks = (e + 255) / 256;
    int agg_blocks  = (int)(((long long)e * 32 + 255) / 256);

    for (int l = 0; l < 2; l++) {
        k_prep<<<prep_blocks, 256>>>(h, l > 0, att + (size_t)l * 2 * DD, n);
        k_edge_max<<<edge_blocks, 256>>>(src, dst, e);
        k_edge_agg<<<agg_blocks, 256>>>(src, dst, e);
    }
    k_final<<<prep_blocks, 256>>>((float*)d_out, n);
}